// round 14
// baseline (speedup 1.0000x reference)
#include <cuda_runtime.h>
#include <math.h>

#define B_SZ 4
#define N_PTS 8192
#define KNN 20
#define NCH 16
#define PAD 32
#define DQ 40                              // per-lane buffer depth
#define NBLK 512                           // knn blocks (= stats partials)

typedef unsigned long long u64;

__device__ float4 g_ps[B_SZ][N_PTS + 2 * PAD];   // sorted packed pts + pads
__device__ int    g_si[B_SZ * N_PTS];            // sorted pos -> original idx
__device__ float  g_dmax[B_SZ * N_PTS];
__device__ double g_p1[NBLK];
__device__ double g_p2[NBLK];
__device__ float  g_mv[2];

// ---- exact bitonic sort of (x, idx) per batch; gather packed array ----
__global__ __launch_bounds__(1024) void sort_kernel(const float* __restrict__ x) {
    extern __shared__ u64 sk[];                  // 64 KB dynamic
    const int b = blockIdx.x;
    const int tid = threadIdx.x;
    const float* xb = x + (size_t)b * 3 * N_PTS;

    for (int i = tid; i < N_PTS; i += 1024) {
        unsigned u = __float_as_uint(xb[i]);
        u = (u & 0x80000000u) ? ~u : (u | 0x80000000u);  // order-preserving
        sk[i] = ((u64)u << 32) | (unsigned)i;
    }
    __syncthreads();
    for (int k = 2; k <= N_PTS; k <<= 1) {
        for (int j = k >> 1; j > 0; j >>= 1) {
            for (int q = tid; q < N_PTS / 2; q += 1024) {
                int i = ((q & ~(j - 1)) << 1) | (q & (j - 1));
                int p = i | j;
                u64 a = sk[i], c = sk[p];
                bool asc = (i & k) == 0;
                if ((a > c) == asc) { sk[i] = c; sk[p] = a; }
            }
            __syncthreads();
        }
    }
    // gather packed candidates in sorted order
    for (int i = tid; i < N_PTS; i += 1024) {
        int oi = (int)(sk[i] & 0xffffffffu);
        float px = xb[oi], py = xb[N_PTS + oi], pz = xb[2 * N_PTS + oi];
        float psq = fmaf(px, px, fmaf(py, py, pz * pz));
        g_ps[b][PAD + i] = make_float4(-2.f * px, -2.f * py, -2.f * pz, psq);
        g_si[b * N_PTS + i] = oi;
    }
    const float INF = __int_as_float(0x7f800000);
    for (int i = tid; i < PAD; i += 1024) {
        g_ps[b][i] = make_float4(2e9f, 0.f, 0.f, INF);                  // px=-1e9
        g_ps[b][PAD + N_PTS + i] = make_float4(-2e9f, 0.f, 0.f, INF);   // px=+1e9
    }
}

__device__ __forceinline__ void insert1(float (&r)[KNN], float v) {
#pragma unroll
    for (int k = KNN - 1; k >= 1; k--)
        r[k] = fminf(r[k], fmaxf(r[k - 1], v));
    r[0] = fminf(r[0], v);
}

__device__ __forceinline__ void drain_buf(float (&r)[KNN], const float* mybuf,
                                          int& cnt, float& r19,
                                          volatile float* tslot) {
    const float INF = __int_as_float(0x7f800000);
    int jmax = (int)__reduce_max_sync(0xffffffffu, (unsigned)cnt);
    for (int j = 0; j < jmax; j++) {
        float v = mybuf[j * 32];
        v = (j < cnt) ? v : INF;
        insert1(r, v);
    }
    cnt = 0;
    float t = fminf(*tslot, r[KNN - 1]);   // racy monotone min: safe upper bound
    *tslot = t;
    r19 = t;
}

// 2 warps per 32-query group: dir1 scans up from gbase, dir0 scans down.
__global__ __launch_bounds__(128, 8) void knn_kernel() {
    __shared__ float  buf[4 * 32 * DQ];          // 20 KB drain buffers
    __shared__ float  thr[2][32];                // shared per-query threshold
    __shared__ float  mb[2][32][21];             // dir1 -> dir0 merge
    __shared__ double red[2][2];

    const int warp = threadIdx.x >> 5, lane = threadIdx.x & 31;
    const int grp = warp >> 1, dir = warp & 1;
    const int gid = blockIdx.x * 2 + grp;        // 0..1023
    const int b = gid >> 8;
    const int gbase = (gid & 255) << 5;

    const float4* P = &g_ps[b][PAD];             // valid for c in [-PAD, N+PAD)
    const int p = gbase + lane;
    float4 qp = P[p];
    const float qx = -0.5f * qp.x, qy = -0.5f * qp.y, qz = -0.5f * qp.z;
    const float qsq = qp.w;

    float* mybuf = buf + warp * 32 * DQ + lane;
    volatile float* ts = &thr[grp][lane];
    const float INF = __int_as_float(0x7f800000);
    if (dir == 0) thr[grp][lane] = INF;
    __syncthreads();

    float r[KNN];
#pragma unroll
    for (int k = 0; k < KNN; k++) r[k] = INF;

    // seed: 32 nearest-in-x on this side, unconditional insert
    {
        int c0 = dir ? gbase : gbase - 32;
        for (int j = 0; j < 32; j++) {
            float4 pc = P[c0 + j];
            insert1(r, fmaf(qx, pc.x, fmaf(qy, pc.y, fmaf(qz, pc.z, pc.w))));
        }
    }
    float r19;
    { float tt = fminf(*ts, r[KNN - 1]); *ts = tt; r19 = tt; }
    int cnt = 0;
    int pos = dir ? gbase + 32 : gbase - 48;     // next 16-chunk start

    while (true) {
        if (dir ? (pos >= N_PTS) : (pos + 15 < 0)) break;   // chunk all-pad
        // stop rule: nearest unprocessed x on this side vs current threshold
        float tg = fminf(r19, *ts);
        float ex = -0.5f * P[dir ? pos : pos + 15].x;
        float dx = ex - qx;
        bool done = dx * dx >= (tg + qsq) * 1.0002f + 1e-12f;  // conservative
        if (__all_sync(0xffffffffu, done)) break;
        if (__any_sync(0xffffffffu, cnt >= DQ - 16))
            drain_buf(r, mybuf, cnt, r19, ts);
        tg = fminf(r19, *ts);
#pragma unroll
        for (int u = 0; u < 16; u++) {
            float4 pc = P[pos + u];              // warp-uniform LDG.128
            float e = fmaf(qx, pc.x, fmaf(qy, pc.y, fmaf(qz, pc.z, pc.w)));
            bool q = e < tg;
            mybuf[cnt * 32] = e;                 // commits only if q
            cnt += (int)q;
        }
        pos += dir ? 16 : -16;
    }
    drain_buf(r, mybuf, cnt, r19, ts);           // tail drain

    // ---- merge the two direction lists (exact top-20 of union) ----
    if (dir == 1) {
#pragma unroll
        for (int k = 0; k < KNN; k++) mb[grp][lane][k] = r[k];
    }
    __syncthreads();

    if (dir == 0) {
#pragma unroll
        for (int k = 0; k < KNN; k++) insert1(r, mb[grp][lane][k]);

        double s1 = 0.0, s2 = 0.0;
#pragma unroll
        for (int k = 0; k < KNN; k++) {
            float d2 = fmaxf(r[k] + qsq, 0.f);
            float d = sqrtf(d2);
            s1 += (double)d;
            s2 += (double)d2;
        }
        int oi = g_si[b * N_PTS + p];
        g_dmax[b * N_PTS + oi] = sqrtf(fmaxf(r[KNN - 1] + qsq, 0.f));

#pragma unroll
        for (int o = 16; o > 0; o >>= 1) {
            s1 += __shfl_xor_sync(0xffffffffu, s1, o);
            s2 += __shfl_xor_sync(0xffffffffu, s2, o);
        }
        if (lane == 0) { red[grp][0] = s1; red[grp][1] = s2; }
    }
    __syncthreads();
    if (threadIdx.x == 0) {
        g_p1[blockIdx.x] = red[0][0] + red[1][0];
        g_p2[blockIdx.x] = red[0][1] + red[1][1];
    }
}

__global__ void stats_kernel() {
    __shared__ double sr1[4], sr2[4];
    int t = threadIdx.x;
    double v1 = 0.0, v2 = 0.0;
#pragma unroll
    for (int i = 0; i < NBLK / 128; i++) {
        v1 += g_p1[t + i * 128];
        v2 += g_p2[t + i * 128];
    }
#pragma unroll
    for (int o = 16; o > 0; o >>= 1) {
        v1 += __shfl_xor_sync(0xffffffffu, v1, o);
        v2 += __shfl_xor_sync(0xffffffffu, v2, o);
    }
    if ((t & 31) == 0) { sr1[t >> 5] = v1; sr2[t >> 5] = v2; }
    __syncthreads();
    if (t == 0) {
        double s1 = sr1[0] + sr1[1] + sr1[2] + sr1[3];
        double s2 = sr2[0] + sr2[1] + sr2[2] + sr2[3];
        const double M = (double)(B_SZ * N_PTS * KNN);
        double m = s1 / M;
        double var = s2 / M - m * m;
        if (var < 0.0) var = 0.0;
        g_mv[0] = (float)m;
        g_mv[1] = (float)var;
    }
}

__global__ __launch_bounds__(256) void out_kernel(const float* __restrict__ conv_w,
                                                  const float* __restrict__ gamma,
                                                  const float* __restrict__ beta,
                                                  float* __restrict__ out) {
    __shared__ float s_s[NCH], s_t[NCH];
    if (threadIdx.x < NCH) {
        int c = threadIdx.x;
        float m = g_mv[0];
        float v = g_mv[1];
        float w = conv_w[c];
        float s = gamma[c] * w * rsqrtf(fmaf(w * w, v, 1e-5f));
        s_s[c] = s;
        s_t[c] = beta[c] - s * m;   // conv_b cancels in training-mode BN
    }
    __syncthreads();

    int q = blockIdx.x * blockDim.x + threadIdx.x;
    int b = q / N_PTS, n = q % N_PTS;
    float dmax = g_dmax[q];
#pragma unroll
    for (int c = 0; c < NCH; c++) {
        float s = s_s[c];
        float knn = (s >= 0.f) ? dmax : 0.f;  // min knn = 0 (self-distance)
        float y = fmaf(s, knn, s_t[c]);
        y = (y >= 0.f) ? y : 0.2f * y;        // LeakyReLU commutes with max_k
        out[((size_t)b * NCH + c) * N_PTS + n] = y;
    }
}

extern "C" void kernel_launch(void* const* d_in, const int* in_sizes, int n_in,
                              void* d_out, int out_size) {
    const float* x      = (const float*)d_in[0];
    const float* conv_w = (const float*)d_in[1];
    const float* gamma  = (const float*)d_in[3];
    const float* beta   = (const float*)d_in[4];
    float* out = (float*)d_out;

    cudaFuncSetAttribute(sort_kernel,
                         cudaFuncAttributeMaxDynamicSharedMemorySize, 65536);
    sort_kernel<<<B_SZ, 1024, 65536>>>(x);
    knn_kernel<<<NBLK, 128>>>();
    stats_kernel<<<1, 128>>>();
    out_kernel<<<(B_SZ * N_PTS) / 256, 256>>>(conv_w, gamma, beta, out);
}

// round 15
// speedup vs baseline: 1.9333x; 1.9333x over previous
#include <cuda_runtime.h>
#include <math.h>

#define B_SZ 4
#define N_PTS 8192
#define KNN 20
#define NCH 16
#define TILE 512
#define NT (N_PTS / TILE)                  // 16 tiles
#define THREADS 128
#define SPLIT 4                            // one split per warp
#define QPB 32                             // queries per block (sorted-consecutive)
#define DQ 24                              // per-lane buffer depth
#define NBLK ((B_SZ * N_PTS) / QPB)        // 1024 knn blocks

typedef unsigned long long u64;

__device__ float4 g_ps[B_SZ][N_PTS];       // x-sorted packed (-2x,-2y,-2z,|p|^2)
__device__ int    g_si[B_SZ * N_PTS];      // sorted pos -> original idx
__device__ float  g_dmax[B_SZ * N_PTS];
__device__ double g_p1[NBLK];
__device__ double g_p2[NBLK];
__device__ float  g_mv[2];

// ---- exact bitonic sort of (x, idx) per batch; gather packed array ----
__global__ __launch_bounds__(1024) void sort_kernel(const float* __restrict__ x) {
    extern __shared__ u64 sk[];                  // 64 KB dynamic
    const int b = blockIdx.x;
    const int tid = threadIdx.x;
    const float* xb = x + (size_t)b * 3 * N_PTS;

    for (int i = tid; i < N_PTS; i += 1024) {
        unsigned u = __float_as_uint(xb[i]);
        u = (u & 0x80000000u) ? ~u : (u | 0x80000000u);  // order-preserving
        sk[i] = ((u64)u << 32) | (unsigned)i;
    }
    __syncthreads();
    for (int k = 2; k <= N_PTS; k <<= 1) {
        for (int j = k >> 1; j > 0; j >>= 1) {
            for (int q = tid; q < N_PTS / 2; q += 1024) {
                int i = ((q & ~(j - 1)) << 1) | (q & (j - 1));
                int p = i | j;
                u64 a = sk[i], c = sk[p];
                bool asc = (i & k) == 0;
                if ((a > c) == asc) { sk[i] = c; sk[p] = a; }
            }
            __syncthreads();
        }
    }
    for (int i = tid; i < N_PTS; i += 1024) {
        int oi = (int)(sk[i] & 0xffffffffu);
        float px = xb[oi], py = xb[N_PTS + oi], pz = xb[2 * N_PTS + oi];
        float psq = fmaf(px, px, fmaf(py, py, pz * pz));
        g_ps[b][i] = make_float4(-2.f * px, -2.f * py, -2.f * pz, psq);
        g_si[b * N_PTS + i] = oi;
    }
}

__device__ __forceinline__ void insert1(float (&r)[KNN], float v) {
#pragma unroll
    for (int k = KNN - 1; k >= 1; k--)
        r[k] = fminf(r[k], fmaxf(r[k - 1], v));
    r[0] = fminf(r[0], v);
}

__device__ __forceinline__ void drain_buf(float (&r)[KNN], const float* mybuf,
                                          int& cnt, float& r19,
                                          volatile float* tslot) {
    const float INF = __int_as_float(0x7f800000);
    int jmax = (int)__reduce_max_sync(0xffffffffu, (unsigned)cnt);
    for (int j = 0; j < jmax; j++) {
        float v = mybuf[j * 32];
        v = (j < cnt) ? v : INF;
        insert1(r, v);
    }
    cnt = 0;
    float t = fminf(*tslot, r[KNN - 1]);   // racy monotone min: safe upper bound
    *tslot = t;
    r19 = t;
}

__global__ __launch_bounds__(THREADS, 7) void knn_kernel() {
    __shared__ float4 sh[TILE];                       // 8 KB
    __shared__ float  buf[4 * 32 * DQ];               // 12 KB; reused for merge
    __shared__ float  thr[QPB];                       // shared per-query threshold

    const int warp = threadIdx.x >> 5, lane = threadIdx.x & 31;
    float* mybuf = buf + warp * 32 * DQ + lane;
    volatile float* thrv = thr;
    const int s = warp;                               // split 0..3

    const int b = blockIdx.x >> 8;                    // 256 groups per batch
    const int gbase = (blockIdx.x & 255) << 5;
    const float4* __restrict__ P = g_ps[b];

    const int p = gbase + lane;                       // sorted query position
    float4 qp = P[p];
    const float qx = -0.5f * qp.x, qy = -0.5f * qp.y, qz = -0.5f * qp.z;
    const float qsq = qp.w;

    const float INF = __int_as_float(0x7f800000);
    float r[KNN];
#pragma unroll
    for (int k = 0; k < KNN; k++) r[k] = INF;
    float r19 = INF;
    int cnt = 0;
    if (threadIdx.x < QPB) thr[threadIdx.x] = INF;

    const int T0 = gbase / TILE;                      // tile containing queries
    int up = T0, dn = T0 - 1;
    bool first = true;

    while (true) {
        __syncthreads();          // thr snapshot stable; sh free for restage
        // uniform tile decision (identical in every warp: lane-consistent data)
        float thd2 = fmaf(thr[lane], 1.001f, fmaf(qsq, 1.001f, 1e-9f));
        bool need_up = false, need_dn = false;
        if (up < NT) {
            if (up == T0) need_up = true;             // query tile: always scan
            else {
                float ex = -0.5f * P[up * TILE].x;    // tile min-x (sorted asc)
                float dx = ex - qx;                   // >= 0 for up > T0
                need_up = !__all_sync(0xffffffffu, dx * dx >= thd2);
            }
        }
        if (dn >= 0) {
            float ex = -0.5f * P[dn * TILE + TILE - 1].x;  // tile max-x
            float dx = qx - ex;                       // >= 0
            need_dn = !__all_sync(0xffffffffu, dx * dx >= thd2);
        }
        int tsel;
        if (need_up && need_dn) tsel = (up - T0 <= T0 - dn) ? up : dn;
        else if (need_up) tsel = up;
        else if (need_dn) tsel = dn;
        else break;
        if (tsel == up) up++; else dn--;

        // cooperative stage: pure float4 copy (already packed & sorted)
        {
            const float4* src = P + tsel * TILE;
            for (int i = threadIdx.x; i < TILE; i += THREADS)
                sh[i] = src[i];
        }
        __syncthreads();

        const float4* shs = sh + s;        // split s scans i ≡ s (mod 4)
        int jstart = 0;
        if (first) {                       // first tile is always T0
            first = false;
            for (int j = 0; j < 32; j++) { // split-disjoint unconditional seed
                float4 pc = shs[j << 2];
                insert1(r, fmaf(qx, pc.x, fmaf(qy, pc.y, fmaf(qz, pc.z, pc.w))));
            }
            float tt = fminf(thrv[lane], r[KNN - 1]);
            thrv[lane] = tt;
            r19 = tt;
            jstart = 32;
        }
        for (int j = jstart; j < TILE / SPLIT; j += 16) {
            if (__any_sync(0xffffffffu, cnt >= DQ - 16))
                drain_buf(r, mybuf, cnt, r19, thrv + lane);
            float tg = fminf(r19, thrv[lane]);
#pragma unroll
            for (int u = 0; u < 16; u++) {
                float4 pc = shs[(j + u) << 2];   // warp-uniform -> broadcast
                float e = fmaf(qx, pc.x, fmaf(qy, pc.y, fmaf(qz, pc.z, pc.w)));
                bool q = e < tg;
                mybuf[cnt * 32] = e;             // commits only if q
                cnt += (int)q;
            }
        }
    }
    drain_buf(r, mybuf, cnt, r19, thrv + lane);  // tail drain

    // ---- merge the 4 split lists per query (exact top-20 of union) ----
    __syncthreads();                       // buf now free -> merge storage
    float* mbuf = buf;                     // [(s-1)*32 + lane]*21 + k (pad 21)
    if (s >= 1) {
#pragma unroll
        for (int k = 0; k < KNN; k++)
            mbuf[((s - 1) * QPB + lane) * 21 + k] = r[k];
    }
    __syncthreads();

    if (s == 0) {
        for (int m = 0; m < SPLIT - 1; m++)
#pragma unroll
            for (int k = 0; k < KNN; k++)
                insert1(r, mbuf[(m * QPB + lane) * 21 + k]);

        // finalize: back to d2-space, clamp, sqrt, stats in double
        double s1 = 0.0, s2 = 0.0;
#pragma unroll
        for (int k = 0; k < KNN; k++) {
            float d2 = fmaxf(r[k] + qsq, 0.f);
            float d = sqrtf(d2);
            s1 += (double)d;
            s2 += (double)d2;
        }
        int oi = g_si[b * N_PTS + p];      // scatter to original order
        g_dmax[b * N_PTS + oi] = sqrtf(fmaxf(r[KNN - 1] + qsq, 0.f));

#pragma unroll
        for (int o = 16; o > 0; o >>= 1) {
            s1 += __shfl_xor_sync(0xffffffffu, s1, o);
            s2 += __shfl_xor_sync(0xffffffffu, s2, o);
        }
        if (lane == 0) {
            g_p1[blockIdx.x] = s1;
            g_p2[blockIdx.x] = s2;
        }
    }
}

__global__ void stats_kernel() {
    __shared__ double sr1[4], sr2[4];
    int t = threadIdx.x;
    double v1 = 0.0, v2 = 0.0;
#pragma unroll
    for (int i = 0; i < NBLK / 128; i++) {
        v1 += g_p1[t + i * 128];
        v2 += g_p2[t + i * 128];
    }
#pragma unroll
    for (int o = 16; o > 0; o >>= 1) {
        v1 += __shfl_xor_sync(0xffffffffu, v1, o);
        v2 += __shfl_xor_sync(0xffffffffu, v2, o);
    }
    if ((t & 31) == 0) { sr1[t >> 5] = v1; sr2[t >> 5] = v2; }
    __syncthreads();
    if (t == 0) {
        double s1 = sr1[0] + sr1[1] + sr1[2] + sr1[3];
        double s2 = sr2[0] + sr2[1] + sr2[2] + sr2[3];
        const double M = (double)(B_SZ * N_PTS * KNN);
        double m = s1 / M;
        double var = s2 / M - m * m;
        if (var < 0.0) var = 0.0;
        g_mv[0] = (float)m;
        g_mv[1] = (float)var;
    }
}

__global__ __launch_bounds__(256) void out_kernel(const float* __restrict__ conv_w,
                                                  const float* __restrict__ gamma,
                                                  const float* __restrict__ beta,
                                                  float* __restrict__ out) {
    __shared__ float s_s[NCH], s_t[NCH];
    if (threadIdx.x < NCH) {
        int c = threadIdx.x;
        float m = g_mv[0];
        float v = g_mv[1];
        float w = conv_w[c];
        float s = gamma[c] * w * rsqrtf(fmaf(w * w, v, 1e-5f));
        s_s[c] = s;
        s_t[c] = beta[c] - s * m;   // conv_b cancels in training-mode BN
    }
    __syncthreads();

    int q = blockIdx.x * blockDim.x + threadIdx.x;
    int b = q / N_PTS, n = q % N_PTS;
    float dmax = g_dmax[q];
#pragma unroll
    for (int c = 0; c < NCH; c++) {
        float s = s_s[c];
        float knn = (s >= 0.f) ? dmax : 0.f;  // min knn = 0 (self-distance)
        float y = fmaf(s, knn, s_t[c]);
        y = (y >= 0.f) ? y : 0.2f * y;        // LeakyReLU commutes with max_k
        out[((size_t)b * NCH + c) * N_PTS + n] = y;
    }
}

extern "C" void kernel_launch(void* const* d_in, const int* in_sizes, int n_in,
                              void* d_out, int out_size) {
    const float* x      = (const float*)d_in[0];
    const float* conv_w = (const float*)d_in[1];
    const float* gamma  = (const float*)d_in[3];
    const float* beta   = (const float*)d_in[4];
    float* out = (float*)d_out;

    cudaFuncSetAttribute(sort_kernel,
                         cudaFuncAttributeMaxDynamicSharedMemorySize, 65536);
    sort_kernel<<<B_SZ, 1024, 65536>>>(x);
    knn_kernel<<<NBLK, THREADS>>>();
    stats_kernel<<<1, 128>>>();
    out_kernel<<<(B_SZ * N_PTS) / 256, 256>>>(conv_w, gamma, beta, out);
}

// round 16
// speedup vs baseline: 2.5754x; 1.3321x over previous
#include <cuda_runtime.h>
#include <math.h>

#define B_SZ 4
#define N_PTS 8192
#define KNN 20
#define NCH 16
#define TILE 512
#define NT (N_PTS / TILE)                  // 16 tiles
#define NBINS 256
#define THREADS 128
#define SPLIT 4                            // one split per warp
#define QPB 32                             // queries per block (bin-consecutive)
#define DQ 24                              // per-lane buffer depth
#define NBLK ((B_SZ * N_PTS) / QPB)        // 1024 knn blocks

__device__ float4 g_ps[B_SZ][N_PTS];       // x-binned packed (-2x,-2y,-2z,|p|^2)
__device__ int    g_si[B_SZ * N_PTS];      // binned pos -> original idx
__device__ int    g_bcur[B_SZ][NBINS];     // bin cursors (offsets, then bumped)
__device__ float  g_xmin[B_SZ], g_xscale[B_SZ];
__device__ float  g_txmin[B_SZ][NT], g_txmax[B_SZ][NT];   // exact tile x-range
__device__ float  g_dmax[B_SZ * N_PTS];
__device__ double g_p1[NBLK];
__device__ double g_p2[NBLK];
__device__ float  g_mv[2];

// ---- pass 1: per-batch x min/max + histogram + serial scan -> cursors ----
__global__ __launch_bounds__(1024) void bin_kernel(const float* __restrict__ x) {
    __shared__ float smin[32], smax[32];
    __shared__ int   hist[NBINS];
    __shared__ float sxmin, sscale;
    const int b = blockIdx.x, tid = threadIdx.x;
    const int warp = tid >> 5, lane = tid & 31;
    const float* xb = x + (size_t)b * 3 * N_PTS;

    float mn = 1e30f, mx = -1e30f;
    for (int i = tid; i < N_PTS; i += 1024) {
        float v = xb[i];
        mn = fminf(mn, v);
        mx = fmaxf(mx, v);
    }
#pragma unroll
    for (int o = 16; o > 0; o >>= 1) {
        mn = fminf(mn, __shfl_xor_sync(0xffffffffu, mn, o));
        mx = fmaxf(mx, __shfl_xor_sync(0xffffffffu, mx, o));
    }
    if (lane == 0) { smin[warp] = mn; smax[warp] = mx; }
    if (tid < NBINS) hist[tid] = 0;
    __syncthreads();
    if (tid == 0) {
        float a = smin[0], c = smax[0];
        for (int i = 1; i < 32; i++) { a = fminf(a, smin[i]); c = fmaxf(c, smax[i]); }
        sxmin = a;
        sscale = (float)NBINS / fmaxf(c - a, 1e-20f) * (1.f - 1e-6f);
        g_xmin[b] = a;
        g_xscale[b] = sscale;
    }
    __syncthreads();
    for (int i = tid; i < N_PTS; i += 1024) {
        int bi = (int)((xb[i] - sxmin) * sscale);
        bi = min(NBINS - 1, max(0, bi));
        atomicAdd(&hist[bi], 1);
    }
    __syncthreads();
    if (tid == 0) {                         // serial exclusive scan (256)
        int acc = 0;
        for (int i = 0; i < NBINS; i++) {
            g_bcur[b][i] = acc;
            acc += hist[i];
        }
    }
}

// ---- pass 2: scatter into binned order ----
__global__ __launch_bounds__(256) void scatter_kernel(const float* __restrict__ x) {
    int idx = blockIdx.x * 256 + threadIdx.x;        // 0 .. B*N-1
    int b = idx >> 13, i = idx & (N_PTS - 1);
    const float* xb = x + (size_t)b * 3 * N_PTS;
    float px = xb[i], py = xb[N_PTS + i], pz = xb[2 * N_PTS + i];
    int bi = (int)((px - g_xmin[b]) * g_xscale[b]);
    bi = min(NBINS - 1, max(0, bi));
    int pos = atomicAdd(&g_bcur[b][bi], 1);
    float psq = fmaf(px, px, fmaf(py, py, pz * pz));
    g_ps[b][pos] = make_float4(-2.f * px, -2.f * py, -2.f * pz, psq);
    g_si[b * N_PTS + pos] = i;
}

// ---- pass 3: exact per-tile x-range ----
__global__ __launch_bounds__(128) void tminmax_kernel() {
    __shared__ float smn[4], smx[4];
    int t = blockIdx.x, b = t / NT, ti = t % NT;
    const float4* P = g_ps[b] + ti * TILE;
    float mn = 1e30f, mx = -1e30f;
    for (int i = threadIdx.x; i < TILE; i += 128) {
        float px = -0.5f * P[i].x;
        mn = fminf(mn, px);
        mx = fmaxf(mx, px);
    }
#pragma unroll
    for (int o = 16; o > 0; o >>= 1) {
        mn = fminf(mn, __shfl_xor_sync(0xffffffffu, mn, o));
        mx = fmaxf(mx, __shfl_xor_sync(0xffffffffu, mx, o));
    }
    int w = threadIdx.x >> 5;
    if ((threadIdx.x & 31) == 0) { smn[w] = mn; smx[w] = mx; }
    __syncthreads();
    if (threadIdx.x == 0) {
        g_txmin[b][ti] = fminf(fminf(smn[0], smn[1]), fminf(smn[2], smn[3]));
        g_txmax[b][ti] = fmaxf(fmaxf(smx[0], smx[1]), fmaxf(smx[2], smx[3]));
    }
}

__device__ __forceinline__ void insert1(float (&r)[KNN], float v) {
#pragma unroll
    for (int k = KNN - 1; k >= 1; k--)
        r[k] = fminf(r[k], fmaxf(r[k - 1], v));
    r[0] = fminf(r[0], v);
}

__device__ __forceinline__ void drain_buf(float (&r)[KNN], const float* mybuf,
                                          int& cnt, float& r19,
                                          volatile float* tslot) {
    const float INF = __int_as_float(0x7f800000);
    int jmax = (int)__reduce_max_sync(0xffffffffu, (unsigned)cnt);
    for (int j = 0; j < jmax; j++) {
        float v = mybuf[j * 32];
        v = (j < cnt) ? v : INF;
        insert1(r, v);
    }
    cnt = 0;
    float t = fminf(*tslot, r[KNN - 1]);   // racy monotone min: safe upper bound
    *tslot = t;
    r19 = t;
}

__global__ __launch_bounds__(THREADS, 7) void knn_kernel() {
    __shared__ float4 sh[TILE];                       // 8 KB
    __shared__ float  buf[4 * 32 * DQ];               // 12 KB; reused for merge
    __shared__ float  thr[QPB];                       // shared per-query threshold

    const int warp = threadIdx.x >> 5, lane = threadIdx.x & 31;
    float* mybuf = buf + warp * 32 * DQ + lane;
    volatile float* thrv = thr;
    const int s = warp;                               // split 0..3

    const int b = blockIdx.x >> 8;                    // 256 groups per batch
    const int gbase = (blockIdx.x & 255) << 5;
    const float4* __restrict__ P = g_ps[b];

    const int p = gbase + lane;                       // binned query position
    float4 qp = P[p];
    const float qx = -0.5f * qp.x, qy = -0.5f * qp.y, qz = -0.5f * qp.z;
    const float qsq = qp.w;

    const float INF = __int_as_float(0x7f800000);
    float r[KNN];
#pragma unroll
    for (int k = 0; k < KNN; k++) r[k] = INF;
    float r19 = INF;
    int cnt = 0;
    if (threadIdx.x < QPB) thr[threadIdx.x] = INF;

    const int T0 = gbase / TILE;                      // tile containing queries
    int up = T0, dn = T0 - 1;
    bool first = true;

    while (true) {
        __syncthreads();          // thr snapshot stable; sh free for restage
        // uniform tile decision (identical in every warp: lane-consistent data)
        float thd2 = fmaf(thr[lane], 1.001f, fmaf(qsq, 1.001f, 1e-9f));
        bool need_up = false, need_dn = false;
        if (up < NT) {
            if (up == T0) need_up = true;             // query tile: always scan
            else {
                float dxe = fmaxf(g_txmin[b][up] - qx, 0.f);  // overlap-safe
                need_up = !__all_sync(0xffffffffu, dxe * dxe >= thd2);
            }
        }
        if (dn >= 0) {
            float dxe = fmaxf(qx - g_txmax[b][dn], 0.f);
            need_dn = !__all_sync(0xffffffffu, dxe * dxe >= thd2);
        }
        int tsel;
        if (need_up && need_dn) tsel = (up - T0 <= T0 - dn) ? up : dn;
        else if (need_up) tsel = up;
        else if (need_dn) tsel = dn;
        else break;
        if (tsel == up) up++; else dn--;

        // cooperative stage: pure float4 copy (already packed)
        {
            const float4* src = P + tsel * TILE;
            for (int i = threadIdx.x; i < TILE; i += THREADS)
                sh[i] = src[i];
        }
        __syncthreads();

        const float4* shs = sh + s;        // split s scans i ≡ s (mod 4)
        int jstart = 0;
        if (first) {                       // first tile is always T0
            first = false;
            for (int j = 0; j < 32; j++) { // split-disjoint unconditional seed
                float4 pc = shs[j << 2];
                insert1(r, fmaf(qx, pc.x, fmaf(qy, pc.y, fmaf(qz, pc.z, pc.w))));
            }
            float tt = fminf(thrv[lane], r[KNN - 1]);
            thrv[lane] = tt;
            r19 = tt;
            jstart = 32;
        }
        for (int j = jstart; j < TILE / SPLIT; j += 16) {
            if (__any_sync(0xffffffffu, cnt >= DQ - 16))
                drain_buf(r, mybuf, cnt, r19, thrv + lane);
            float tg = fminf(r19, thrv[lane]);
#pragma unroll
            for (int u = 0; u < 16; u++) {
                float4 pc = shs[(j + u) << 2];   // warp-uniform -> broadcast
                float e = fmaf(qx, pc.x, fmaf(qy, pc.y, fmaf(qz, pc.z, pc.w)));
                bool q = e < tg;
                mybuf[cnt * 32] = e;             // commits only if q
                cnt += (int)q;
            }
        }
    }
    drain_buf(r, mybuf, cnt, r19, thrv + lane);  // tail drain

    // ---- merge the 4 split lists per query (exact top-20 of union) ----
    __syncthreads();                       // buf now free -> merge storage
    float* mbuf = buf;                     // [(s-1)*32 + lane]*21 + k (pad 21)
    if (s >= 1) {
#pragma unroll
        for (int k = 0; k < KNN; k++)
            mbuf[((s - 1) * QPB + lane) * 21 + k] = r[k];
    }
    __syncthreads();

    if (s == 0) {
        for (int m = 0; m < SPLIT - 1; m++)
#pragma unroll
            for (int k = 0; k < KNN; k++)
                insert1(r, mbuf[(m * QPB + lane) * 21 + k]);

        // finalize: back to d2-space, clamp, sqrt, stats in double
        double s1 = 0.0, s2 = 0.0;
#pragma unroll
        for (int k = 0; k < KNN; k++) {
            float d2 = fmaxf(r[k] + qsq, 0.f);
            float d = sqrtf(d2);
            s1 += (double)d;
            s2 += (double)d2;
        }
        int oi = g_si[b * N_PTS + p];      // scatter to original order
        g_dmax[b * N_PTS + oi] = sqrtf(fmaxf(r[KNN - 1] + qsq, 0.f));

#pragma unroll
        for (int o = 16; o > 0; o >>= 1) {
            s1 += __shfl_xor_sync(0xffffffffu, s1, o);
            s2 += __shfl_xor_sync(0xffffffffu, s2, o);
        }
        if (lane == 0) {
            g_p1[blockIdx.x] = s1;
            g_p2[blockIdx.x] = s2;
        }
    }
}

__global__ void stats_kernel() {
    __shared__ double sr1[4], sr2[4];
    int t = threadIdx.x;
    double v1 = 0.0, v2 = 0.0;
#pragma unroll
    for (int i = 0; i < NBLK / 128; i++) {
        v1 += g_p1[t + i * 128];
        v2 += g_p2[t + i * 128];
    }
#pragma unroll
    for (int o = 16; o > 0; o >>= 1) {
        v1 += __shfl_xor_sync(0xffffffffu, v1, o);
        v2 += __shfl_xor_sync(0xffffffffu, v2, o);
    }
    if ((t & 31) == 0) { sr1[t >> 5] = v1; sr2[t >> 5] = v2; }
    __syncthreads();
    if (t == 0) {
        double s1 = sr1[0] + sr1[1] + sr1[2] + sr1[3];
        double s2 = sr2[0] + sr2[1] + sr2[2] + sr2[3];
        const double M = (double)(B_SZ * N_PTS * KNN);
        double m = s1 / M;
        double var = s2 / M - m * m;
        if (var < 0.0) var = 0.0;
        g_mv[0] = (float)m;
        g_mv[1] = (float)var;
    }
}

__global__ __launch_bounds__(256) void out_kernel(const float* __restrict__ conv_w,
                                                  const float* __restrict__ gamma,
                                                  const float* __restrict__ beta,
                                                  float* __restrict__ out) {
    __shared__ float s_s[NCH], s_t[NCH];
    if (threadIdx.x < NCH) {
        int c = threadIdx.x;
        float m = g_mv[0];
        float v = g_mv[1];
        float w = conv_w[c];
        float s = gamma[c] * w * rsqrtf(fmaf(w * w, v, 1e-5f));
        s_s[c] = s;
        s_t[c] = beta[c] - s * m;   // conv_b cancels in training-mode BN
    }
    __syncthreads();

    int q = blockIdx.x * blockDim.x + threadIdx.x;
    int b = q / N_PTS, n = q % N_PTS;
    float dmax = g_dmax[q];
#pragma unroll
    for (int c = 0; c < NCH; c++) {
        float s = s_s[c];
        float knn = (s >= 0.f) ? dmax : 0.f;  // min knn = 0 (self-distance)
        float y = fmaf(s, knn, s_t[c]);
        y = (y >= 0.f) ? y : 0.2f * y;        // LeakyReLU commutes with max_k
        out[((size_t)b * NCH + c) * N_PTS + n] = y;
    }
}

extern "C" void kernel_launch(void* const* d_in, const int* in_sizes, int n_in,
                              void* d_out, int out_size) {
    const float* x      = (const float*)d_in[0];
    const float* conv_w = (const float*)d_in[1];
    const float* gamma  = (const float*)d_in[3];
    const float* beta   = (const float*)d_in[4];
    float* out = (float*)d_out;

    bin_kernel<<<B_SZ, 1024>>>(x);
    scatter_kernel<<<(B_SZ * N_PTS) / 256, 256>>>(x);
    tminmax_kernel<<<B_SZ * NT, 128>>>();
    knn_kernel<<<NBLK, THREADS>>>();
    stats_kernel<<<1, 128>>>();
    out_kernel<<<(B_SZ * N_PTS) / 256, 256>>>(conv_w, gamma, beta, out);
}

// round 17
// speedup vs baseline: 2.7734x; 1.0769x over previous
#include <cuda_runtime.h>
#include <math.h>

#define B_SZ 4
#define N_PTS 8192
#define KNN 20
#define NCH 16
#define TILE 256
#define NT (N_PTS / TILE)                  // 32 tiles
#define NBINS 256
#define THREADS 128
#define SPLIT 4                            // one split per warp
#define QPB 32                             // queries per block (bin-consecutive)
#define DQ 24                              // per-lane buffer depth
#define NBLK ((B_SZ * N_PTS) / QPB)        // 1024 knn blocks

__device__ float4 g_ps[B_SZ][N_PTS];       // x-binned packed (-2x,-2y,-2z,|p|^2)
__device__ int    g_si[B_SZ * N_PTS];      // binned pos -> original idx
__device__ int    g_bcur[B_SZ][NBINS];     // bin cursors
__device__ float  g_xmin[B_SZ], g_xscale[B_SZ];
__device__ float  g_txmin[B_SZ][NT], g_txmax[B_SZ][NT];   // exact tile x-range
__device__ float  g_dmax[B_SZ * N_PTS];
__device__ double g_p1[NBLK];
__device__ double g_p2[NBLK];
__device__ float  g_mv[2];

// ---- pass 1: per-batch x min/max + histogram + serial scan -> cursors ----
__global__ __launch_bounds__(1024) void bin_kernel(const float* __restrict__ x) {
    __shared__ float smin[32], smax[32];
    __shared__ int   hist[NBINS];
    __shared__ float sxmin, sscale;
    const int b = blockIdx.x, tid = threadIdx.x;
    const int warp = tid >> 5, lane = tid & 31;
    const float* xb = x + (size_t)b * 3 * N_PTS;

    float mn = 1e30f, mx = -1e30f;
    for (int i = tid; i < N_PTS; i += 1024) {
        float v = xb[i];
        mn = fminf(mn, v);
        mx = fmaxf(mx, v);
    }
#pragma unroll
    for (int o = 16; o > 0; o >>= 1) {
        mn = fminf(mn, __shfl_xor_sync(0xffffffffu, mn, o));
        mx = fmaxf(mx, __shfl_xor_sync(0xffffffffu, mx, o));
    }
    if (lane == 0) { smin[warp] = mn; smax[warp] = mx; }
    if (tid < NBINS) hist[tid] = 0;
    __syncthreads();
    if (tid == 0) {
        float a = smin[0], c = smax[0];
        for (int i = 1; i < 32; i++) { a = fminf(a, smin[i]); c = fmaxf(c, smax[i]); }
        sxmin = a;
        sscale = (float)NBINS / fmaxf(c - a, 1e-20f) * (1.f - 1e-6f);
        g_xmin[b] = a;
        g_xscale[b] = sscale;
    }
    __syncthreads();
    for (int i = tid; i < N_PTS; i += 1024) {
        int bi = (int)((xb[i] - sxmin) * sscale);
        bi = min(NBINS - 1, max(0, bi));
        atomicAdd(&hist[bi], 1);
    }
    __syncthreads();
    if (tid == 0) {                         // serial exclusive scan (256)
        int acc = 0;
        for (int i = 0; i < NBINS; i++) {
            g_bcur[b][i] = acc;
            acc += hist[i];
        }
    }
}

// ---- pass 2: scatter into binned order ----
__global__ __launch_bounds__(256) void scatter_kernel(const float* __restrict__ x) {
    int idx = blockIdx.x * 256 + threadIdx.x;        // 0 .. B*N-1
    int b = idx >> 13, i = idx & (N_PTS - 1);
    const float* xb = x + (size_t)b * 3 * N_PTS;
    float px = xb[i], py = xb[N_PTS + i], pz = xb[2 * N_PTS + i];
    int bi = (int)((px - g_xmin[b]) * g_xscale[b]);
    bi = min(NBINS - 1, max(0, bi));
    int pos = atomicAdd(&g_bcur[b][bi], 1);
    float psq = fmaf(px, px, fmaf(py, py, pz * pz));
    g_ps[b][pos] = make_float4(-2.f * px, -2.f * py, -2.f * pz, psq);
    g_si[b * N_PTS + pos] = i;
}

// ---- pass 3: exact per-tile x-range ----
__global__ __launch_bounds__(128) void tminmax_kernel() {
    __shared__ float smn[4], smx[4];
    int t = blockIdx.x, b = t / NT, ti = t % NT;
    const float4* P = g_ps[b] + ti * TILE;
    float mn = 1e30f, mx = -1e30f;
    for (int i = threadIdx.x; i < TILE; i += 128) {
        float px = -0.5f * P[i].x;
        mn = fminf(mn, px);
        mx = fmaxf(mx, px);
    }
#pragma unroll
    for (int o = 16; o > 0; o >>= 1) {
        mn = fminf(mn, __shfl_xor_sync(0xffffffffu, mn, o));
        mx = fmaxf(mx, __shfl_xor_sync(0xffffffffu, mx, o));
    }
    int w = threadIdx.x >> 5;
    if ((threadIdx.x & 31) == 0) { smn[w] = mn; smx[w] = mx; }
    __syncthreads();
    if (threadIdx.x == 0) {
        g_txmin[b][ti] = fminf(fminf(smn[0], smn[1]), fminf(smn[2], smn[3]));
        g_txmax[b][ti] = fmaxf(fmaxf(smx[0], smx[1]), fmaxf(smx[2], smx[3]));
    }
}

__device__ __forceinline__ void insert1(float (&r)[KNN], float v) {
#pragma unroll
    for (int k = KNN - 1; k >= 1; k--)
        r[k] = fminf(r[k], fmaxf(r[k - 1], v));
    r[0] = fminf(r[0], v);
}

__device__ __forceinline__ void drain_buf(float (&r)[KNN], const float* mybuf,
                                          int& cnt, float& r19,
                                          volatile float* tslot) {
    const float INF = __int_as_float(0x7f800000);
    int jmax = (int)__reduce_max_sync(0xffffffffu, (unsigned)cnt);
    for (int j = 0; j < jmax; j++) {
        float v = mybuf[j * 32];
        v = (j < cnt) ? v : INF;
        insert1(r, v);
    }
    cnt = 0;
    float t = fminf(*tslot, r[KNN - 1]);   // racy monotone min: safe upper bound
    *tslot = t;
    r19 = t;
}

__global__ __launch_bounds__(THREADS, 7) void knn_kernel() {
    __shared__ float4 sh[TILE];                       // 4 KB
    __shared__ float  buf[4 * 32 * DQ];               // 12 KB; reused for merge
    __shared__ float  thr[QPB];                       // shared per-query threshold

    const int warp = threadIdx.x >> 5, lane = threadIdx.x & 31;
    float* mybuf = buf + warp * 32 * DQ + lane;
    volatile float* thrv = thr;
    const int s = warp;                               // split 0..3

    // center-out group ordering: heaviest (x-median) groups get low bids
    const int b = blockIdx.x >> 8;                    // 256 groups per batch
    const int i256 = blockIdx.x & 255;
    const int grp = (i256 & 1) ? (127 - (i256 >> 1)) : (128 + (i256 >> 1));
    const int gbase = grp << 5;
    const float4* __restrict__ P = g_ps[b];

    const int p = gbase + lane;                       // binned query position
    float4 qp = P[p];
    const float qx = -0.5f * qp.x, qy = -0.5f * qp.y, qz = -0.5f * qp.z;
    const float qsq = qp.w;

    const float INF = __int_as_float(0x7f800000);
    float r[KNN];
#pragma unroll
    for (int k = 0; k < KNN; k++) r[k] = INF;
    float r19 = INF;
    int cnt = 0;
    if (threadIdx.x < QPB) thr[threadIdx.x] = INF;

    const int T0 = gbase / TILE;                      // tile containing queries
    int up = T0, dn = T0 - 1;
    bool first = true;

    while (true) {
        __syncthreads();          // thr snapshot stable; sh free for restage
        float thd2 = fmaf(thr[lane], 1.001f, fmaf(qsq, 1.001f, 1e-9f));
        bool need_up = false, need_dn = false;
        if (up < NT) {
            if (up == T0) need_up = true;
            else {
                float dxe = fmaxf(g_txmin[b][up] - qx, 0.f);
                need_up = !__all_sync(0xffffffffu, dxe * dxe >= thd2);
            }
        }
        if (dn >= 0) {
            float dxe = fmaxf(qx - g_txmax[b][dn], 0.f);
            need_dn = !__all_sync(0xffffffffu, dxe * dxe >= thd2);
        }
        int tsel;
        if (need_up && need_dn) tsel = (up - T0 <= T0 - dn) ? up : dn;
        else if (need_up) tsel = up;
        else if (need_dn) tsel = dn;
        else break;
        if (tsel == up) up++; else dn--;

        {   // cooperative stage: pure float4 copy
            const float4* src = P + tsel * TILE;
            for (int i = threadIdx.x; i < TILE; i += THREADS)
                sh[i] = src[i];
        }
        __syncthreads();

        const float4* shs = sh + s;        // split s scans i ≡ s (mod 4)
        int jstart = 0;
        if (first) {                       // first tile is always T0
            first = false;
            for (int j = 0; j < 32; j++) {
                float4 pc = shs[j << 2];
                insert1(r, fmaf(qx, pc.x, fmaf(qy, pc.y, fmaf(qz, pc.z, pc.w))));
            }
            float tt = fminf(thrv[lane], r[KNN - 1]);
            thrv[lane] = tt;
            r19 = tt;
            jstart = 32;
        }
        for (int j = jstart; j < TILE / SPLIT; j += 16) {
            if (__any_sync(0xffffffffu, cnt >= DQ - 16))
                drain_buf(r, mybuf, cnt, r19, thrv + lane);
            float tg = fminf(r19, thrv[lane]);
#pragma unroll
            for (int u = 0; u < 16; u++) {
                float4 pc = shs[(j + u) << 2];   // warp-uniform -> broadcast
                float e = fmaf(qx, pc.x, fmaf(qy, pc.y, fmaf(qz, pc.z, pc.w)));
                bool q = e < tg;
                mybuf[cnt * 32] = e;             // commits only if q
                cnt += (int)q;
            }
        }
    }
    drain_buf(r, mybuf, cnt, r19, thrv + lane);  // tail drain

    // ---- parallel 2-level merge (exact top-20 of union of 4 splits) ----
    __syncthreads();                       // buf now free -> merge storage
    float* mbuf = buf;                     // [w*32 + lane]*21 + k (pad 21)
    if (s == 1 || s == 3) {
#pragma unroll
        for (int k = 0; k < KNN; k++)
            mbuf[((s >> 1) * QPB + lane) * 21 + k] = r[k];
    }
    __syncthreads();
    if (s == 0 || s == 2) {                // w0<-w1 and w2<-w3 in parallel
        int src = s >> 1;
#pragma unroll
        for (int k = 0; k < KNN; k++)
            insert1(r, mbuf[(src * QPB + lane) * 21 + k]);
    }
    __syncthreads();
    if (s == 2) {
#pragma unroll
        for (int k = 0; k < KNN; k++)
            mbuf[lane * 21 + k] = r[k];
    }
    __syncthreads();

    if (s == 0) {
#pragma unroll
        for (int k = 0; k < KNN; k++)
            insert1(r, mbuf[lane * 21 + k]);

        // finalize: back to d2-space, clamp, sqrt, stats in double
        double s1 = 0.0, s2 = 0.0;
#pragma unroll
        for (int k = 0; k < KNN; k++) {
            float d2 = fmaxf(r[k] + qsq, 0.f);
            float d = sqrtf(d2);
            s1 += (double)d;
            s2 += (double)d2;
        }
        int oi = g_si[b * N_PTS + p];      // scatter to original order
        g_dmax[b * N_PTS + oi] = sqrtf(fmaxf(r[KNN - 1] + qsq, 0.f));

#pragma unroll
        for (int o = 16; o > 0; o >>= 1) {
            s1 += __shfl_xor_sync(0xffffffffu, s1, o);
            s2 += __shfl_xor_sync(0xffffffffu, s2, o);
        }
        if (lane == 0) {
            g_p1[blockIdx.x] = s1;
            g_p2[blockIdx.x] = s2;
        }
    }
}

__global__ void stats_kernel() {
    __shared__ double sr1[4], sr2[4];
    int t = threadIdx.x;
    double v1 = 0.0, v2 = 0.0;
#pragma unroll
    for (int i = 0; i < NBLK / 128; i++) {
        v1 += g_p1[t + i * 128];
        v2 += g_p2[t + i * 128];
    }
#pragma unroll
    for (int o = 16; o > 0; o >>= 1) {
        v1 += __shfl_xor_sync(0xffffffffu, v1, o);
        v2 += __shfl_xor_sync(0xffffffffu, v2, o);
    }
    if ((t & 31) == 0) { sr1[t >> 5] = v1; sr2[t >> 5] = v2; }
    __syncthreads();
    if (t == 0) {
        double s1 = sr1[0] + sr1[1] + sr1[2] + sr1[3];
        double s2 = sr2[0] + sr2[1] + sr2[2] + sr2[3];
        const double M = (double)(B_SZ * N_PTS * KNN);
        double m = s1 / M;
        double var = s2 / M - m * m;
        if (var < 0.0) var = 0.0;
        g_mv[0] = (float)m;
        g_mv[1] = (float)var;
    }
}

__global__ __launch_bounds__(256) void out_kernel(const float* __restrict__ conv_w,
                                                  const float* __restrict__ gamma,
                                                  const float* __restrict__ beta,
                                                  float* __restrict__ out) {
    __shared__ float s_s[NCH], s_t[NCH];
    if (threadIdx.x < NCH) {
        int c = threadIdx.x;
        float m = g_mv[0];
        float v = g_mv[1];
        float w = conv_w[c];
        float s = gamma[c] * w * rsqrtf(fmaf(w * w, v, 1e-5f));
        s_s[c] = s;
        s_t[c] = beta[c] - s * m;   // conv_b cancels in training-mode BN
    }
    __syncthreads();

    int q = blockIdx.x * blockDim.x + threadIdx.x;
    int b = q / N_PTS, n = q % N_PTS;
    float dmax = g_dmax[q];
#pragma unroll
    for (int c = 0; c < NCH; c++) {
        float s = s_s[c];
        float knn = (s >= 0.f) ? dmax : 0.f;  // min knn = 0 (self-distance)
        float y = fmaf(s, knn, s_t[c]);
        y = (y >= 0.f) ? y : 0.2f * y;        // LeakyReLU commutes with max_k
        out[((size_t)b * NCH + c) * N_PTS + n] = y;
    }
}

extern "C" void kernel_launch(void* const* d_in, const int* in_sizes, int n_in,
                              void* d_out, int out_size) {
    const float* x      = (const float*)d_in[0];
    const float* conv_w = (const float*)d_in[1];
    const float* gamma  = (const float*)d_in[3];
    const float* beta   = (const float*)d_in[4];
    float* out = (float*)d_out;

    bin_kernel<<<B_SZ, 1024>>>(x);
    scatter_kernel<<<(B_SZ * N_PTS) / 256, 256>>>(x);
    tminmax_kernel<<<B_SZ * NT, 128>>>();
    knn_kernel<<<NBLK, THREADS>>>();
    stats_kernel<<<1, 128>>>();
    out_kernel<<<(B_SZ * N_PTS) / 256, 256>>>(conv_w, gamma, beta, out);
}